// round 3
// baseline (speedup 1.0000x reference)
#include <cuda_runtime.h>

#define D       128
#define NREL    48
#define NB      8
#define NENT    50000
#define NSPEC   64
#define NEDGE   600000
#define KACC    (NB * D)          // 1024
#define KTOT    (KACC + D)        // 1152
#define BM      64
#define BK      32
#define NTILES  ((NENT + BM - 1) / BM)   // 782
#define NCHUNK  (KTOT / BK)              // 36

// ---------------- device scratch (static __device__, no allocations) -------
__device__ int   g_cnt[NREL * NENT];     // per (rel, dst) edge count
__device__ int   g_deg[NENT];            // per dst total degree
__device__ int   g_off[NENT + 1];        // CSR offsets
__device__ int   g_cur[NENT];            // scatter cursors
__device__ int   g_pk[NEDGE];            // dst-sorted packed (src | type<<16)
__device__ float g_nm[NEDGE];            // dst-sorted 1/cnt
__device__ float g_acc[(size_t)NENT * KTOT];  // [N][1152] aggregated features

__device__ __forceinline__ int clampi(int v, int lo, int hi) {
    return v < lo ? lo : (v > hi ? hi : v);
}

// ---------------- zero counters ----------------
__global__ void k_zero() {
    int total = NREL * NENT + NENT;
    for (int i = blockIdx.x * blockDim.x + threadIdx.x; i < total;
         i += gridDim.x * blockDim.x) {
        if (i < NREL * NENT) g_cnt[i] = 0;
        else                 g_deg[i - NREL * NENT] = 0;
    }
}

// ---------------- histogram (edge_index/edge_type are int32) ----------------
__global__ void k_count(const int* __restrict__ ei,
                        const int* __restrict__ et) {
    int e = blockIdx.x * blockDim.x + threadIdx.x;
    if (e >= NEDGE) return;
    int dst = clampi(ei[NEDGE + e], 0, NENT - 1);
    int typ = clampi(et[e], 0, NREL - 1);
    atomicAdd(&g_cnt[typ * NENT + dst], 1);
    atomicAdd(&g_deg[dst], 1);
}

// ---------------- single-block exclusive scan over g_deg ----------------
__global__ void k_scan() {
    __shared__ int sh[1024];
    int tid = threadIdx.x;
    int carry = 0;
    for (int base = 0; base < NENT; base += 1024) {
        int i = base + tid;
        int v = (i < NENT) ? g_deg[i] : 0;
        sh[tid] = v;
        __syncthreads();
        for (int off = 1; off < 1024; off <<= 1) {
            int t = sh[tid];
            if (tid >= off) t += sh[tid - off];
            __syncthreads();
            sh[tid] = t;
            __syncthreads();
        }
        int incl = sh[tid];
        if (i < NENT) {
            int ex = carry + incl - v;
            g_off[i] = ex;
            g_cur[i] = ex;
        }
        carry += sh[1023];
        __syncthreads();
    }
    if (tid == 0) g_off[NENT] = carry;
}

// ---------------- scatter edges into dst-sorted order ----------------
__global__ void k_scatter(const int* __restrict__ ei,
                          const int* __restrict__ et) {
    int e = blockIdx.x * blockDim.x + threadIdx.x;
    if (e >= NEDGE) return;
    int src = clampi(ei[e], 0, NENT - 1);
    int dst = clampi(ei[NEDGE + e], 0, NENT - 1);
    int typ = clampi(et[e], 0, NREL - 1);
    int pos = atomicAdd(&g_cur[dst], 1);
    if (pos >= NEDGE) return;
    g_pk[pos] = src | (typ << 16);
    int c = g_cnt[typ * NENT + dst];
    g_nm[pos] = 1.0f / (float)(c > 1 ? c : 1);
}

// ---------------- aggregation: one warp per node ----------------
// acc[n][b*128+k] = sum_{e:dst=n} comp[type,b]/cnt * x[src,k];  acc[n][1024+k]=x[n,k]
__global__ __launch_bounds__(256)
void k_agg(const float* __restrict__ x, const float* __restrict__ comp) {
    __shared__ float comps[NREL * NB];
    int tid = threadIdx.x;
    for (int t = tid; t < NREL * NB; t += 256) comps[t] = comp[t];
    __syncthreads();

    int w    = tid >> 5;
    int lane = tid & 31;
    int n    = blockIdx.x * 8 + w;
    if (n >= NENT) return;

    float4 av[NB];
#pragma unroll
    for (int b = 0; b < NB; b++) av[b] = make_float4(0.f, 0.f, 0.f, 0.f);

    int s = g_off[n], e = g_off[n + 1];
    for (int idx = s; idx < e; idx++) {
        int   pk = g_pk[idx];
        float nm = g_nm[idx];
        int src = pk & 0xFFFF;
        int typ = (pk >> 16) & 0x3F;
        float4 xv = *((const float4*)(x + (size_t)src * D) + lane);
#pragma unroll
        for (int b = 0; b < NB; b++) {
            float c = comps[typ * NB + b] * nm;
            av[b].x += c * xv.x;
            av[b].y += c * xv.y;
            av[b].z += c * xv.z;
            av[b].w += c * xv.w;
        }
    }

    float* row = g_acc + (size_t)n * KTOT;
#pragma unroll
    for (int b = 0; b < NB; b++)
        *((float4*)(row + b * D) + lane) = av[b];
    // copy own x row into the tail (root part of the fused GEMM)
    *((float4*)(row + KACC) + lane) = *((const float4*)(x + (size_t)n * D) + lane);
}

// ---------------- tiled SIMT fp32 GEMM: out = g_acc @ [basis;root] + bias ---
__global__ __launch_bounds__(256)
void k_gemm(const float* __restrict__ basis, const float* __restrict__ root,
            const float* __restrict__ bias, float* __restrict__ out) {
    __shared__ float As[BK][BM];     // 8 KB  (k-major for broadcast reads)
    __shared__ float Bs[BK][D];      // 16 KB

    int tid = threadIdx.x;
    int m0  = blockIdx.x * BM;
    int ty  = tid >> 5;              // 0..7 : node group
    int tx  = tid & 31;              // 0..31: col group (4 cols)

    float4 bias4 = *((const float4*)bias + tx);
    float4 acc[8];
#pragma unroll
    for (int i = 0; i < 8; i++) acc[i] = bias4;

    for (int ch = 0; ch < NCHUNK; ch++) {
        int kc = ch * BK;
        // load A tile: 64 m x 32 k, transposed into As[k][m]
#pragma unroll
        for (int i = 0; i < 2; i++) {
            int f  = tid * 2 + i;          // 0..511 float4 ids
            int m  = f >> 3;               // 8 float4 per (m, 32k) row
            int k4 = f & 7;
            float4 v = make_float4(0.f, 0.f, 0.f, 0.f);
            if (m0 + m < NENT)
                v = *(const float4*)(g_acc + (size_t)(m0 + m) * KTOT + kc + k4 * 4);
            As[k4 * 4 + 0][m] = v.x;
            As[k4 * 4 + 1][m] = v.y;
            As[k4 * 4 + 2][m] = v.z;
            As[k4 * 4 + 3][m] = v.w;
        }
        // load B tile: 32 k x 128 c from basis (k<1024) or root
        const float* Bsrc = (kc < KACC) ? (basis + (size_t)kc * D)
                                        : (root + (size_t)(kc - KACC) * D);
#pragma unroll
        for (int i = 0; i < 4; i++) {
            int f  = tid * 4 + i;          // 0..1023 float4 ids
            int kk = f >> 5;
            int c4 = f & 31;
            *(float4*)&Bs[kk][c4 * 4] =
                *(const float4*)(Bsrc + (size_t)kk * D + c4 * 4);
        }
        __syncthreads();

#pragma unroll
        for (int kk = 0; kk < BK; kk++) {
            float4 b = *(float4*)&Bs[kk][tx * 4];
            float4 a0 = *(float4*)&As[kk][ty * 8];
            float4 a1 = *(float4*)&As[kk][ty * 8 + 4];
            acc[0].x += a0.x * b.x; acc[0].y += a0.x * b.y; acc[0].z += a0.x * b.z; acc[0].w += a0.x * b.w;
            acc[1].x += a0.y * b.x; acc[1].y += a0.y * b.y; acc[1].z += a0.y * b.z; acc[1].w += a0.y * b.w;
            acc[2].x += a0.z * b.x; acc[2].y += a0.z * b.y; acc[2].z += a0.z * b.z; acc[2].w += a0.z * b.w;
            acc[3].x += a0.w * b.x; acc[3].y += a0.w * b.y; acc[3].z += a0.w * b.z; acc[3].w += a0.w * b.w;
            acc[4].x += a1.x * b.x; acc[4].y += a1.x * b.y; acc[4].z += a1.x * b.z; acc[4].w += a1.x * b.w;
            acc[5].x += a1.y * b.x; acc[5].y += a1.y * b.y; acc[5].z += a1.y * b.z; acc[5].w += a1.y * b.w;
            acc[6].x += a1.z * b.x; acc[6].y += a1.z * b.y; acc[6].z += a1.z * b.z; acc[6].w += a1.z * b.w;
            acc[7].x += a1.w * b.x; acc[7].y += a1.w * b.y; acc[7].z += a1.w * b.z; acc[7].w += a1.w * b.w;
        }
        __syncthreads();
    }

#pragma unroll
    for (int i = 0; i < 8; i++) {
        int m = m0 + ty * 8 + i;
        if (m < NENT)
            *((float4*)(out + (size_t)m * D) + tx) = acc[i];
    }
}

// ---------------- special embedding concat ----------------
__global__ void k_special(const float* __restrict__ sp, float* __restrict__ out) {
    int i = blockIdx.x * blockDim.x + threadIdx.x;
    if (i < NSPEC * D) out[(size_t)NENT * D + i] = sp[i];
}

// ---------------- launch ----------------
extern "C" void kernel_launch(void* const* d_in, const int* in_sizes, int n_in,
                              void* d_out, int out_size) {
    const int*   ei    = (const int*)d_in[0];      // int32 (JAX x64 disabled)
    const int*   et    = (const int*)d_in[1];      // int32
    const float* x     = (const float*)d_in[2];
    const float* basis = (const float*)d_in[3];
    const float* comp  = (const float*)d_in[4];
    const float* root  = (const float*)d_in[5];
    const float* bias  = (const float*)d_in[6];
    const float* spec  = (const float*)d_in[7];
    float*       out   = (float*)d_out;

    k_zero<<<2048, 256>>>();
    k_count<<<(NEDGE + 255) / 256, 256>>>(ei, et);
    k_scan<<<1, 1024>>>();
    k_scatter<<<(NEDGE + 255) / 256, 256>>>(ei, et);
    k_agg<<<(NENT + 7) / 8, 256>>>(x, comp);
    k_gemm<<<NTILES, 256>>>(basis, root, bias, out);
    k_special<<<(NSPEC * D + 255) / 256, 256>>>(spec, out);
}

// round 5
// speedup vs baseline: 2.1682x; 2.1682x over previous
#include <cuda_runtime.h>
#include <cuda_bf16.h>
#include <cstdint>

#define D       128
#define NREL    48
#define NB      8
#define NENT    50000
#define NSPEC   64
#define NEDGE   600000
#define KACC    1024
#define KTOT    1152
#define MTILE   128
#define NTIL    391                 // ceil(50000/128)
#define MPAD    (NTIL * MTILE)      // 50048
#define KC      32
#define NCH     (KTOT / KC)         // 36
#define SSTR    40                  // smem row stride (bf16): 80B, uint4-aligned

// ---------------- device scratch ----------------
__device__ int   g_cnt[NREL * NENT];
__device__ int   g_deg[NENT];
__device__ int   g_off[NENT];
__device__ int   g_cur[NENT];
__device__ int   g_total;
__device__ int   g_pk[NEDGE];
__device__ float g_nm[NEDGE];
__device__ __nv_bfloat16 g_Ahi[(size_t)MPAD * KTOT];   // pad rows stay zero
__device__ __nv_bfloat16 g_Alo[(size_t)MPAD * KTOT];
__device__ __nv_bfloat16 g_Bhi[(size_t)D * KTOT];      // B^T [n][k]
__device__ __nv_bfloat16 g_Blo[(size_t)D * KTOT];

__device__ __forceinline__ int clampi(int v, int lo, int hi) {
    return v < lo ? lo : (v > hi ? hi : v);
}
__device__ __forceinline__ uint32_t smem_u32(const void* p) {
    uint32_t a;
    asm("{ .reg .u64 t; cvta.to.shared.u64 t, %1; cvt.u32.u64 %0, t; }"
        : "=r"(a) : "l"(p));
    return a;
}
__device__ __forceinline__ void ldsm4(uint32_t* r, uint32_t addr) {
    asm volatile("ldmatrix.sync.aligned.m8n8.x4.shared.b16 {%0,%1,%2,%3}, [%4];"
        : "=r"(r[0]), "=r"(r[1]), "=r"(r[2]), "=r"(r[3]) : "r"(addr));
}
__device__ __forceinline__ void mma_bf16(float* c, const uint32_t* a,
                                         const uint32_t* b) {
    asm volatile(
        "mma.sync.aligned.m16n8k16.row.col.f32.bf16.bf16.f32 "
        "{%0,%1,%2,%3}, {%4,%5,%6,%7}, {%8,%9}, {%0,%1,%2,%3};"
        : "+f"(c[0]), "+f"(c[1]), "+f"(c[2]), "+f"(c[3])
        : "r"(a[0]), "r"(a[1]), "r"(a[2]), "r"(a[3]), "r"(b[0]), "r"(b[1]));
}

// bf16 two-term split of a float4, packed stores
__device__ __forceinline__ void split_store4(__nv_bfloat16* hi, __nv_bfloat16* lo,
                                             float4 v) {
    __nv_bfloat16 h0 = __float2bfloat16(v.x), h1 = __float2bfloat16(v.y);
    __nv_bfloat16 h2 = __float2bfloat16(v.z), h3 = __float2bfloat16(v.w);
    __nv_bfloat16 l0 = __float2bfloat16(v.x - __bfloat162float(h0));
    __nv_bfloat16 l1 = __float2bfloat16(v.y - __bfloat162float(h1));
    __nv_bfloat16 l2 = __float2bfloat16(v.z - __bfloat162float(h2));
    __nv_bfloat16 l3 = __float2bfloat16(v.w - __bfloat162float(h3));
    union { __nv_bfloat16 b[4]; uint2 u; } H, L;
    H.b[0] = h0; H.b[1] = h1; H.b[2] = h2; H.b[3] = h3;
    L.b[0] = l0; L.b[1] = l1; L.b[2] = l2; L.b[3] = l3;
    *(uint2*)hi = H.u;
    *(uint2*)lo = L.u;
}

// ---------------- preprocessing ----------------
__global__ void k_zero() {
    int total = NREL * NENT + NENT + 1;
    for (int i = blockIdx.x * blockDim.x + threadIdx.x; i < total;
         i += gridDim.x * blockDim.x) {
        if (i < NREL * NENT)             g_cnt[i] = 0;
        else if (i < NREL * NENT + NENT) g_deg[i - NREL * NENT] = 0;
        else                             g_total = 0;
    }
}

__global__ void k_count(const int* __restrict__ ei, const int* __restrict__ et) {
    int e = blockIdx.x * blockDim.x + threadIdx.x;
    if (e >= NEDGE) return;
    int dst = clampi(ei[NEDGE + e], 0, NENT - 1);
    int typ = clampi(et[e], 0, NREL - 1);
    atomicAdd(&g_cnt[typ * NENT + dst], 1);
    atomicAdd(&g_deg[dst], 1);
}

// segment offsets: warp scan + one atomic per warp (order-free, disjoint)
__global__ void k_off() {
    int n = blockIdx.x * blockDim.x + threadIdx.x;
    int lane = threadIdx.x & 31;
    int deg = (n < NENT) ? g_deg[n] : 0;
    int incl = deg;
#pragma unroll
    for (int o = 1; o < 32; o <<= 1) {
        int t = __shfl_up_sync(0xFFFFFFFFu, incl, o);
        if (lane >= o) incl += t;
    }
    int tot = __shfl_sync(0xFFFFFFFFu, incl, 31);
    int base = 0;
    if (lane == 31) base = atomicAdd(&g_total, tot);
    base = __shfl_sync(0xFFFFFFFFu, base, 31);
    if (n < NENT) {
        int st = base + incl - deg;
        g_off[n] = st;
        g_cur[n] = st;
    }
}

__global__ void k_scatter(const int* __restrict__ ei, const int* __restrict__ et) {
    int e = blockIdx.x * blockDim.x + threadIdx.x;
    if (e >= NEDGE) return;
    int src = clampi(ei[e], 0, NENT - 1);
    int dst = clampi(ei[NEDGE + e], 0, NENT - 1);
    int typ = clampi(et[e], 0, NREL - 1);
    int pos = atomicAdd(&g_cur[dst], 1);
    if (pos >= NEDGE) return;
    g_pk[pos] = src | (typ << 16);
    int c = g_cnt[typ * NENT + dst];
    g_nm[pos] = 1.0f / (float)(c > 1 ? c : 1);
}

// ---------------- aggregation: warp per node, bf16 hi/lo output ---------------
__global__ __launch_bounds__(256)
void k_agg(const float* __restrict__ x, const float* __restrict__ comp) {
    __shared__ float comps[NREL * NB];
    int tid = threadIdx.x;
    for (int t = tid; t < NREL * NB; t += 256) comps[t] = comp[t];
    __syncthreads();

    int w = tid >> 5, lane = tid & 31;
    int n = blockIdx.x * 8 + w;
    if (n >= NENT) return;

    float4 av[NB];
#pragma unroll
    for (int b = 0; b < NB; b++) av[b] = make_float4(0.f, 0.f, 0.f, 0.f);

    int s = g_off[n], e = s + g_deg[n];
    for (int idx = s; idx < e; idx++) {
        int   pk = g_pk[idx];
        float nm = g_nm[idx];
        int src = pk & 0xFFFF;
        int typ = (pk >> 16) & 0x3F;
        float4 xv = *((const float4*)(x + (size_t)src * D) + lane);
#pragma unroll
        for (int b = 0; b < NB; b++) {
            float c = comps[typ * NB + b] * nm;
            av[b].x += c * xv.x; av[b].y += c * xv.y;
            av[b].z += c * xv.z; av[b].w += c * xv.w;
        }
    }

    size_t rb = (size_t)n * KTOT;
#pragma unroll
    for (int b = 0; b < NB; b++)
        split_store4(g_Ahi + rb + b * D + lane * 4, g_Alo + rb + b * D + lane * 4, av[b]);
    float4 xv = *((const float4*)(x + (size_t)n * D) + lane);
    split_store4(g_Ahi + rb + KACC + lane * 4, g_Alo + rb + KACC + lane * 4, xv);
}

// ---------------- B^T hi/lo: g_B*[n][k] = [basis;root][k][n] ----------------
__global__ void k_prepB(const float* __restrict__ basis, const float* __restrict__ root) {
    int i = blockIdx.x * blockDim.x + threadIdx.x;
    if (i >= D * KTOT) return;
    int n = i / KTOT, k = i % KTOT;
    float v = (k < KACC) ? basis[(size_t)k * D + n] : root[(size_t)(k - KACC) * D + n];
    __nv_bfloat16 h = __float2bfloat16(v);
    g_Bhi[i] = h;
    g_Blo[i] = __float2bfloat16(v - __bfloat162float(h));
}

// ---------------- bf16 HMMA GEMM (Markidis 3-combo split) --------------------
// CTA: 128x128 C tile, 8 warps = 2(m) x 4(n), each warp 64x32.
__global__ __launch_bounds__(256)
void k_gemm(const float* __restrict__ bias, float* __restrict__ out) {
    __shared__ __align__(16) __nv_bfloat16 sA[2][MTILE][SSTR];   // hi/lo, 20 KB
    __shared__ __align__(16) __nv_bfloat16 sB[2][D][SSTR];       // hi/lo, 20 KB

    int tid = threadIdx.x, wid = tid >> 5, lane = tid & 31;
    int m0 = blockIdx.x * MTILE;
    int wm = wid & 1;          // m offset 64*wm
    int wn = wid >> 1;         // n offset 32*wn

    float c[4][4][4];
#pragma unroll
    for (int mt = 0; mt < 4; mt++)
#pragma unroll
        for (int nt = 0; nt < 4; nt++)
#pragma unroll
            for (int r = 0; r < 4; r++) c[mt][nt][r] = 0.f;

    for (int ch = 0; ch < NCH; ch++) {
        int kc = ch * KC;
        // stage: 128 rows x 32 k per array; 512 uint4 per array, 2 per thread
#pragma unroll
        for (int i = 0; i < 2; i++) {
            int cix = tid + i * 256;
            int r = cix >> 2, q = cix & 3;
            size_t ga = (size_t)(m0 + r) * KTOT + kc + q * 8;
            size_t gb = (size_t)r * KTOT + kc + q * 8;
            *(uint4*)&sA[0][r][q * 8] = *(const uint4*)(g_Ahi + ga);
            *(uint4*)&sA[1][r][q * 8] = *(const uint4*)(g_Alo + ga);
            *(uint4*)&sB[0][r][q * 8] = *(const uint4*)(g_Bhi + gb);
            *(uint4*)&sB[1][r][q * 8] = *(const uint4*)(g_Blo + gb);
        }
        __syncthreads();

#pragma unroll
        for (int ks = 0; ks < 2; ks++) {
            uint32_t ah[4][4], al[4][4], bh[2][4], bl[2][4];
            int arow = wm * 64 + (lane & 15);
            int acol = ks * 16 + (lane >> 4) * 8;
#pragma unroll
            for (int mt = 0; mt < 4; mt++) {
                ldsm4(ah[mt], smem_u32(&sA[0][arow + mt * 16][acol]));
                ldsm4(al[mt], smem_u32(&sA[1][arow + mt * 16][acol]));
            }
            int brow = wn * 32 + (lane & 7) + ((lane >> 4) << 3);
            int bcol = ks * 16 + ((lane >> 3) & 1) * 8;
#pragma unroll
            for (int p = 0; p < 2; p++) {
                ldsm4(bh[p], smem_u32(&sB[0][brow + p * 16][bcol]));
                ldsm4(bl[p], smem_u32(&sB[1][brow + p * 16][bcol]));
            }
#pragma unroll
            for (int mt = 0; mt < 4; mt++)
#pragma unroll
                for (int nt = 0; nt < 4; nt++) {
                    const uint32_t* bhp = &bh[nt >> 1][(nt & 1) * 2];
                    const uint32_t* blp = &bl[nt >> 1][(nt & 1) * 2];
                    mma_bf16(c[mt][nt], ah[mt], bhp);
                    mma_bf16(c[mt][nt], ah[mt], blp);
                    mma_bf16(c[mt][nt], al[mt], bhp);
                }
        }
        __syncthreads();
    }

    // epilogue: c frag (m16n8): lane owns rows l/4 and l/4+8, cols (l%4)*2..+1
#pragma unroll
    for (int mt = 0; mt < 4; mt++) {
#pragma unroll
        for (int nt = 0; nt < 4; nt++) {
            int m = m0 + wm * 64 + mt * 16 + (lane >> 2);
            int n = wn * 32 + nt * 8 + (lane & 3) * 2;
            float b0 = __ldg(bias + n), b1 = __ldg(bias + n + 1);
            if (m < NENT) {
                float2 v = make_float2(c[mt][nt][0] + b0, c[mt][nt][1] + b1);
                *(float2*)(out + (size_t)m * D + n) = v;
            }
            if (m + 8 < NENT) {
                float2 v = make_float2(c[mt][nt][2] + b0, c[mt][nt][3] + b1);
                *(float2*)(out + (size_t)(m + 8) * D + n) = v;
            }
        }
    }
}

// ---------------- special embedding concat ----------------
__global__ void k_special(const float* __restrict__ sp, float* __restrict__ out) {
    int i = blockIdx.x * blockDim.x + threadIdx.x;
    if (i < NSPEC * D) out[(size_t)NENT * D + i] = sp[i];
}

// ---------------- launch ----------------
extern "C" void kernel_launch(void* const* d_in, const int* in_sizes, int n_in,
                              void* d_out, int out_size) {
    const int*   ei    = (const int*)d_in[0];
    const int*   et    = (const int*)d_in[1];
    const float* x     = (const float*)d_in[2];
    const float* basis = (const float*)d_in[3];
    const float* comp  = (const float*)d_in[4];
    const float* root  = (const float*)d_in[5];
    const float* bias  = (const float*)d_in[6];
    const float* spec  = (const float*)d_in[7];
    float*       out   = (float*)d_out;

    k_zero<<<2048, 256>>>();
    k_count<<<(NEDGE + 255) / 256, 256>>>(ei, et);
    k_off<<<(NENT + 255) / 256, 256>>>();
    k_scatter<<<(NEDGE + 255) / 256, 256>>>(ei, et);
    k_agg<<<(NENT + 7) / 8, 256>>>(x, comp);
    k_prepB<<<(D * KTOT + 255) / 256, 256>>>(basis, root);
    k_gemm<<<NTIL, 256>>>(bias, out);
    k_special<<<(NSPEC * D + 255) / 256, 256>>>(spec, out);
}